// round 1
// baseline (speedup 1.0000x reference)
#include <cuda_runtime.h>
#include <math.h>

#define Bn 8
#define Sn 1024
#define Cn 1024
#define Hn 16
#define Dn 64
#define Mn (Bn*Sn)        // 8192
#define N1 (3*Cn)         // 3072

// ---- scratch (static device globals; no allocation) ----
__device__ float g_qkv[(size_t)Mn * N1];        // (B,S,3C)    ~100 MB
__device__ float g_q[(size_t)Bn*Hn*Sn*Dn];      // (B,H,S,D)   ~33 MB
__device__ float g_k[(size_t)Bn*Hn*Sn*Dn];
__device__ float g_v[(size_t)Bn*Hn*Sn*Dn];
__device__ float g_att[(size_t)Mn * Cn];        // (B,S,C)     ~33 MB

// ============================================================
// Tiled SGEMM with fused bias: C[M,N] = A[M,K] @ B[K,N] + bias[N]
// 128x128 block tile, K-tile 16, 256 threads, 8x8 per thread.
// All dims are exact multiples (M%128==0, N%128==0, K%16==0).
// ============================================================
__global__ __launch_bounds__(256) void sgemm_bias(
    const float* __restrict__ A, const float* __restrict__ Bm,
    const float* __restrict__ bias, float* __restrict__ Cout,
    int Mdim, int Ndim, int Kdim)
{
    __shared__ float As[16][128];
    __shared__ float Bs[16][128];

    const int tid  = threadIdx.x;
    const int brow = blockIdx.y * 128;
    const int bcol = blockIdx.x * 128;
    const int trow = (tid >> 4) * 8;   // 0..120
    const int tcol = (tid & 15) * 8;   // 0..120

    float acc[8][8];
    #pragma unroll
    for (int i = 0; i < 8; i++)
        #pragma unroll
        for (int j = 0; j < 8; j++) acc[i][j] = 0.f;

    for (int k0 = 0; k0 < Kdim; k0 += 16) {
        // A tile: 128 rows x 16 cols -> store transposed As[k][m]
        #pragma unroll
        for (int i = 0; i < 2; i++) {
            int lid = tid + i * 256;          // 0..511 float4 slots
            int r   = lid >> 2;               // 0..127
            int c4  = lid & 3;                // 0..3
            float4 v = *(const float4*)&A[(size_t)(brow + r) * Kdim + k0 + c4 * 4];
            As[c4*4+0][r] = v.x;
            As[c4*4+1][r] = v.y;
            As[c4*4+2][r] = v.z;
            As[c4*4+3][r] = v.w;
        }
        // B tile: 16 rows x 128 cols -> Bs[k][n]
        #pragma unroll
        for (int i = 0; i < 2; i++) {
            int lid = tid + i * 256;          // 0..511
            int r   = lid >> 5;               // 0..15
            int c4  = lid & 31;               // 0..31
            *(float4*)&Bs[r][c4*4] =
                *(const float4*)&Bm[(size_t)(k0 + r) * Ndim + bcol + c4 * 4];
        }
        __syncthreads();

        #pragma unroll
        for (int kk = 0; kk < 16; kk++) {
            float4 a0 = *(const float4*)&As[kk][trow];
            float4 a1 = *(const float4*)&As[kk][trow + 4];
            float4 b0 = *(const float4*)&Bs[kk][tcol];
            float4 b1 = *(const float4*)&Bs[kk][tcol + 4];
            float a[8] = {a0.x,a0.y,a0.z,a0.w,a1.x,a1.y,a1.z,a1.w};
            float b[8] = {b0.x,b0.y,b0.z,b0.w,b1.x,b1.y,b1.z,b1.w};
            #pragma unroll
            for (int i = 0; i < 8; i++)
                #pragma unroll
                for (int j = 0; j < 8; j++)
                    acc[i][j] = fmaf(a[i], b[j], acc[i][j]);
        }
        __syncthreads();
    }

    #pragma unroll
    for (int i = 0; i < 8; i++) {
        size_t r = (size_t)(brow + trow + i) * Ndim + bcol + tcol;
        #pragma unroll
        for (int j = 0; j < 8; j += 4) {
            float4 v;
            v.x = acc[i][j+0] + bias[bcol + tcol + j + 0];
            v.y = acc[i][j+1] + bias[bcol + tcol + j + 1];
            v.z = acc[i][j+2] + bias[bcol + tcol + j + 2];
            v.w = acc[i][j+3] + bias[bcol + tcol + j + 3];
            *(float4*)&Cout[r + j] = v;
        }
    }
}

// ============================================================
// RoPE + scatter: qkv (B,S,3,H,D) -> g_q/g_k (rope'd), g_v, all (B,H,S,D)
// One thread per (b,h,s,pair i in [0,32)): handles d=i and d=i+32.
// ============================================================
__global__ __launch_bounds__(256) void rope_scatter_kernel()
{
    int idx = blockIdx.x * blockDim.x + threadIdx.x;  // B*H*S*32 = 4,194,304
    int i = idx & 31;
    int s = (idx >> 5)  & (Sn - 1);
    int h = (idx >> 15) & (Hn - 1);
    int b =  idx >> 19;

    const float* row = g_qkv + (size_t)(b * Sn + s) * N1;
    int base = h * Dn;

    float inv = expf(-(logf(10000.f) / Dn) * (2.f * i));
    float ang = (float)s * inv;
    float sn, cs;
    sincosf(ang, &sn, &cs);

    float q1 = row[0*Cn + base + i];
    float q2 = row[0*Cn + base + i + 32];
    float k1 = row[1*Cn + base + i];
    float k2 = row[1*Cn + base + i + 32];
    float v1 = row[2*Cn + base + i];
    float v2 = row[2*Cn + base + i + 32];

    size_t o = ((size_t)(b * Hn + h) * Sn + s) * Dn;
    g_q[o + i]      = q1 * cs - q2 * sn;
    g_q[o + i + 32] = q2 * cs + q1 * sn;
    g_k[o + i]      = k1 * cs - k2 * sn;
    g_k[o + i + 32] = k2 * cs + k1 * sn;
    g_v[o + i]      = v1;
    g_v[o + i + 32] = v2;
}

// ============================================================
// Flash attention: grid (qtile=8, bh=128), 128 threads/block,
// one thread per q row. q and o accumulator in registers,
// K/V tiles of 16 rows staged in smem (broadcast reads).
// Writes g_att in (B,S,C) layout so the proj GEMM reads it directly.
// ============================================================
#define TJ 16

__global__ __launch_bounds__(128) void attn_kernel()
{
    const int bh = blockIdx.y;                 // 0..127  (b*16 + h)
    const int qt = blockIdx.x;                 // 0..7
    const int t  = threadIdx.x;                // 0..127
    const int row = qt * 128 + t;              // q row within (b,h)

    __shared__ float Ks[TJ * Dn];
    __shared__ float Vs[TJ * Dn];

    const float* qptr = g_q + ((size_t)bh * Sn + row) * Dn;
    float q[Dn];
    #pragma unroll
    for (int i = 0; i < 16; i++) {
        float4 v = *(const float4*)(qptr + i * 4);
        q[4*i] = v.x; q[4*i+1] = v.y; q[4*i+2] = v.z; q[4*i+3] = v.w;
    }

    float o[Dn];
    #pragma unroll
    for (int d = 0; d < Dn; d++) o[d] = 0.f;
    float m = -1e30f, l = 0.f;
    const float scale = 0.125f;   // 1/sqrt(64)

    for (int j0 = 0; j0 < Sn; j0 += TJ) {
        const float4* kt = (const float4*)(g_k + ((size_t)bh * Sn + j0) * Dn);
        const float4* vt = (const float4*)(g_v + ((size_t)bh * Sn + j0) * Dn);
        __syncthreads();
        // TJ*Dn floats = 256 float4 per buffer; 128 threads -> 2 each
        #pragma unroll
        for (int i = 0; i < (TJ * Dn / 4) / 128; i++) {
            int idx = t + i * 128;
            ((float4*)Ks)[idx] = kt[idx];
            ((float4*)Vs)[idx] = vt[idx];
        }
        __syncthreads();

        float s[TJ];
        float mt = m;
        #pragma unroll
        for (int j = 0; j < TJ; j++) {
            float acc = 0.f;
            const float4* krow = (const float4*)(Ks + j * Dn);
            #pragma unroll
            for (int d4 = 0; d4 < 16; d4++) {
                float4 kv = krow[d4];
                acc = fmaf(q[4*d4+0], kv.x, acc);
                acc = fmaf(q[4*d4+1], kv.y, acc);
                acc = fmaf(q[4*d4+2], kv.z, acc);
                acc = fmaf(q[4*d4+3], kv.w, acc);
            }
            s[j] = acc * scale;
            mt = fmaxf(mt, s[j]);
        }

        float corr = __expf(m - mt);
        m = mt;
        l *= corr;
        #pragma unroll
        for (int d = 0; d < Dn; d++) o[d] *= corr;

        #pragma unroll
        for (int j = 0; j < TJ; j++) {
            float p = __expf(s[j] - m);
            l += p;
            const float4* vrow = (const float4*)(Vs + j * Dn);
            #pragma unroll
            for (int d4 = 0; d4 < 16; d4++) {
                float4 vv = vrow[d4];
                o[4*d4+0] = fmaf(p, vv.x, o[4*d4+0]);
                o[4*d4+1] = fmaf(p, vv.y, o[4*d4+1]);
                o[4*d4+2] = fmaf(p, vv.z, o[4*d4+2]);
                o[4*d4+3] = fmaf(p, vv.w, o[4*d4+3]);
            }
        }
    }

    float inv_l = 1.f / l;
    int b = bh >> 4, h = bh & 15;
    float* optr = g_att + (size_t)(b * Sn + row) * Cn + h * Dn;
    #pragma unroll
    for (int i = 0; i < 16; i++) {
        float4 v;
        v.x = o[4*i+0] * inv_l;
        v.y = o[4*i+1] * inv_l;
        v.z = o[4*i+2] * inv_l;
        v.w = o[4*i+3] * inv_l;
        *(float4*)(optr + 4 * i) = v;
    }
}

// ============================================================
// Launch
// ============================================================
extern "C" void kernel_launch(void* const* d_in, const int* in_sizes, int n_in,
                              void* d_out, int out_size)
{
    const float* x      = (const float*)d_in[0];
    const float* W_qkv  = (const float*)d_in[1];
    const float* b_qkv  = (const float*)d_in[2];
    const float* W_proj = (const float*)d_in[3];
    const float* b_proj = (const float*)d_in[4];
    float* out = (float*)d_out;

    float *p_qkv, *p_att;
    cudaGetSymbolAddress((void**)&p_qkv, g_qkv);
    cudaGetSymbolAddress((void**)&p_att, g_att);

    // 1) QKV GEMM + bias: (8192,3072) = x(8192,1024) @ W_qkv(1024,3072)
    {
        dim3 grid(N1 / 128, Mn / 128);
        sgemm_bias<<<grid, 256>>>(x, W_qkv, b_qkv, p_qkv, Mn, N1, Cn);
    }
    // 2) RoPE + transpose into (B,H,S,D)
    {
        int total = Bn * Hn * Sn * 32;
        rope_scatter_kernel<<<total / 256, 256>>>();
    }
    // 3) Flash attention -> g_att (B,S,C)
    {
        dim3 grid(Sn / 128, Bn * Hn);
        attn_kernel<<<grid, 128>>>();
    }
    // 4) Output projection: out(8192,1024) = g_att @ W_proj + b_proj
    {
        dim3 grid(Cn / 128, Mn / 128);
        sgemm_bias<<<grid, 256>>>(p_att, W_proj, b_proj, out, Mn, Cn, Cn);
    }
}

// round 3
// speedup vs baseline: 1.3505x; 1.3505x over previous
#include <cuda_runtime.h>
#include <cuda_bf16.h>
#include <math.h>
#include <cstdint>

#define Bn 8
#define Sn 1024
#define Cn 1024
#define Hn 16
#define Dn 64
#define Mn (Bn*Sn)        // 8192
#define N1 (3*Cn)         // 3072
#define KP (3*Cn)         // extended K for hi/lo-split GEMM

// ---- scratch (static device globals; no allocation) ----
__device__ float g_qkv[(size_t)Mn * N1];            // (B,S,3C)
__device__ float g_q[(size_t)Bn*Hn*Sn*Dn];          // (B,H,S,D)
__device__ float g_k[(size_t)Bn*Hn*Sn*Dn];
__device__ float g_v[(size_t)Bn*Hn*Sn*Dn];
__device__ float g_att[(size_t)Mn * Cn];            // (B,S,C)
__device__ __nv_bfloat16 g_A3[(size_t)Mn * KP];     // split A (50MB), reused
__device__ __nv_bfloat16 g_B3[(size_t)N1 * KP];     // split B^T (18MB), reused

// ============================================================
// helpers
// ============================================================
__device__ __forceinline__ uint32_t smem_u32(const void* p) {
    uint32_t a;
    asm("{ .reg .u64 t; cvta.to.shared.u64 t, %1; cvt.u32.u64 %0, t; }"
        : "=r"(a) : "l"(p));
    return a;
}
__device__ __forceinline__ void cpa16(uint32_t s, const void* g) {
    asm volatile("cp.async.cg.shared.global [%0], [%1], 16;" :: "r"(s), "l"(g));
}
__device__ __forceinline__ void ldm4(uint32_t addr, uint32_t& r0, uint32_t& r1,
                                     uint32_t& r2, uint32_t& r3) {
    asm volatile("ldmatrix.sync.aligned.m8n8.x4.shared.b16 {%0,%1,%2,%3}, [%4];"
                 : "=r"(r0), "=r"(r1), "=r"(r2), "=r"(r3) : "r"(addr));
}
__device__ __forceinline__ void mma_bf16(float* d, const uint32_t* a,
                                         uint32_t b0, uint32_t b1) {
    asm volatile(
        "mma.sync.aligned.m16n8k16.row.col.f32.bf16.bf16.f32 "
        "{%0,%1,%2,%3}, {%4,%5,%6,%7}, {%8,%9}, {%0,%1,%2,%3};"
        : "+f"(d[0]), "+f"(d[1]), "+f"(d[2]), "+f"(d[3])
        : "r"(a[0]), "r"(a[1]), "r"(a[2]), "r"(a[3]), "r"(b0), "r"(b1));
}

// ============================================================
// Split conversions: a = hi + lo (bf16 each)
// A3 = [hi | lo | hi], B3 = [hi | hi | lo]  (K'=3K)
// => single GEMM over K' gives hi*hi + lo*hi + hi*lo
// ============================================================
__global__ __launch_bounds__(256) void conv_A(const float* __restrict__ A,
                                              __nv_bfloat16* __restrict__ A3, int Kdim)
{
    int idx = blockIdx.x * 256 + threadIdx.x;
    int r = idx / Kdim, k = idx - r * Kdim;
    float v = A[idx];
    __nv_bfloat16 hi = __float2bfloat16(v);
    __nv_bfloat16 lo = __float2bfloat16(v - __bfloat162float(hi));
    size_t base = (size_t)r * (3 * Kdim);
    A3[base + k] = hi;
    A3[base + Kdim + k] = lo;
    A3[base + 2 * Kdim + k] = hi;
}

// W: (K, N) row-major -> B3: (N, 3K)
__global__ __launch_bounds__(256) void conv_B(const float* __restrict__ W,
                                              __nv_bfloat16* __restrict__ B3,
                                              int Kdim, int Ndim)
{
    __shared__ float t[32][33];
    int k0 = blockIdx.x * 32, n0 = blockIdx.y * 32;
    int tx = threadIdx.x & 31, ty = threadIdx.x >> 5;   // 32 x 8
    #pragma unroll
    for (int i = 0; i < 4; i++)
        t[ty + i * 8][tx] = W[(size_t)(k0 + ty + i * 8) * Ndim + n0 + tx];
    __syncthreads();
    #pragma unroll
    for (int i = 0; i < 4; i++) {
        int n = ty + i * 8;
        float v = t[tx][n];   // = W[k0+tx][n0+n]
        __nv_bfloat16 hi = __float2bfloat16(v);
        __nv_bfloat16 lo = __float2bfloat16(v - __bfloat162float(hi));
        size_t base = (size_t)(n0 + n) * (3 * Kdim);
        B3[base + k0 + tx] = hi;
        B3[base + Kdim + k0 + tx] = hi;
        B3[base + 2 * Kdim + k0 + tx] = lo;
    }
}

// ============================================================
// HMMA bf16 GEMM: C[M,N] = A3[M,K'] @ B3[N,K']^T + bias
// 128x128 CTA tile, K-tile 64, double-buffered cp.async,
// 8 warps (2x4), warp tile 64x32, m16n8k16 mma.sync.
// Smem rows padded to 144B -> conflict-free ldmatrix.
// ============================================================
#define KT 64
#define ROWB 144                       // bytes per padded smem row (128 data + 16 pad)
#define TILEB (128 * ROWB)             // one operand tile
#define GM_SMEM (4 * TILEB)            // 2 bufs x (A + B) = 73728 B

__global__ __launch_bounds__(256) void gemm_mma(
    const __nv_bfloat16* __restrict__ A, const __nv_bfloat16* __restrict__ B,
    const float* __restrict__ bias, float* __restrict__ C,
    int Ndim, int Kp)
{
    extern __shared__ char smraw[];
    const uint32_t sb = smem_u32(smraw);
    const int tid = threadIdx.x;
    const int wid = tid >> 5, lane = tid & 31;
    const int brow = blockIdx.y * 128, bcol = blockIdx.x * 128;
    const int warpM = (wid >> 2) * 64;       // 0 or 64
    const int warpN = (wid & 3) * 32;        // 0..96

    float acc[4][4][4];
    #pragma unroll
    for (int i = 0; i < 4; i++)
        #pragma unroll
        for (int j = 0; j < 4; j++)
            #pragma unroll
            for (int e = 0; e < 4; e++) acc[i][j][e] = 0.f;

    const int NT = Kp / KT;

    auto load_tile = [&](int kc, int buf) {
        uint32_t ab = sb + buf * (2 * TILEB);
        uint32_t bb = ab + TILEB;
        const __nv_bfloat16* Ag = A + (size_t)brow * Kp + kc * KT;
        const __nv_bfloat16* Bg = B + (size_t)bcol * Kp + kc * KT;
        #pragma unroll
        for (int i = 0; i < 4; i++) {
            int slot = i * 256 + tid;          // 0..1023
            int r = slot >> 3, c = slot & 7;   // row 0..127, 16B chunk 0..7
            uint32_t so = (uint32_t)(r * ROWB + c * 16);
            cpa16(ab + so, Ag + (size_t)r * Kp + c * 8);
            cpa16(bb + so, Bg + (size_t)r * Kp + c * 8);
        }
        asm volatile("cp.async.commit_group;" ::: "memory");
    };

    load_tile(0, 0);

    const int lm = lane & 15, lh = lane >> 4;

    for (int kt = 0; kt < NT; kt++) {
        int cur = kt & 1;
        if (kt + 1 < NT) load_tile(kt + 1, cur ^ 1);

        if (kt + 1 < NT)
            asm volatile("cp.async.wait_group 1;" ::: "memory");
        else
            asm volatile("cp.async.wait_group 0;" ::: "memory");
        __syncthreads();

        uint32_t ab = sb + cur * (2 * TILEB);
        uint32_t bb = ab + TILEB;
        uint32_t aAddr = ab + (uint32_t)((warpM + lm) * ROWB + lh * 16);
        uint32_t bAddr = bb + (uint32_t)((warpN + lm) * ROWB + lh * 16);

        #pragma unroll
        for (int ks = 0; ks < 4; ks++) {       // 4 x k16
            uint32_t afr[4][4];
            #pragma unroll
            for (int mf = 0; mf < 4; mf++)
                ldm4(aAddr + mf * 16 * ROWB + ks * 32,
                     afr[mf][0], afr[mf][1], afr[mf][2], afr[mf][3]);
            uint32_t bfr[4][2];
            #pragma unroll
            for (int nb = 0; nb < 2; nb++) {
                uint32_t r0, r1, r2, r3;
                ldm4(bAddr + nb * 16 * ROWB + ks * 32, r0, r1, r2, r3);
                bfr[nb * 2 + 0][0] = r0; bfr[nb * 2 + 0][1] = r2;
                bfr[nb * 2 + 1][0] = r1; bfr[nb * 2 + 1][1] = r3;
            }
            #pragma unroll
            for (int mf = 0; mf < 4; mf++)
                #pragma unroll
                for (int nf = 0; nf < 4; nf++)
                    mma_bf16(acc[mf][nf], afr[mf], bfr[nf][0], bfr[nf][1]);
        }
        __syncthreads();
    }

    // epilogue: + bias, fp32 store
    #pragma unroll
    for (int mf = 0; mf < 4; mf++) {
        int grow = brow + warpM + mf * 16 + (lane >> 2);
        #pragma unroll
        for (int nf = 0; nf < 4; nf++) {
            int gcol = bcol + warpN + nf * 8 + (lane & 3) * 2;
            float bx = bias[gcol], by = bias[gcol + 1];
            float* d = acc[mf][nf];
            float2 v0 = {d[0] + bx, d[1] + by};
            float2 v1 = {d[2] + bx, d[3] + by};
            *(float2*)&C[(size_t)grow * Ndim + gcol] = v0;
            *(float2*)&C[(size_t)(grow + 8) * Ndim + gcol] = v1;
        }
    }
}

// ============================================================
// RoPE + scatter (unchanged)
// ============================================================
__global__ __launch_bounds__(256) void rope_scatter_kernel()
{
    int idx = blockIdx.x * blockDim.x + threadIdx.x;
    int i = idx & 31;
    int s = (idx >> 5)  & (Sn - 1);
    int h = (idx >> 15) & (Hn - 1);
    int b =  idx >> 19;

    const float* row = g_qkv + (size_t)(b * Sn + s) * N1;
    int base = h * Dn;

    float inv = expf(-(logf(10000.f) / Dn) * (2.f * i));
    float ang = (float)s * inv;
    float sn, cs;
    sincosf(ang, &sn, &cs);

    float q1 = row[0*Cn + base + i];
    float q2 = row[0*Cn + base + i + 32];
    float k1 = row[1*Cn + base + i];
    float k2 = row[1*Cn + base + i + 32];
    float v1 = row[2*Cn + base + i];
    float v2 = row[2*Cn + base + i + 32];

    size_t o = ((size_t)(b * Hn + h) * Sn + s) * Dn;
    g_q[o + i]      = q1 * cs - q2 * sn;
    g_q[o + i + 32] = q2 * cs + q1 * sn;
    g_k[o + i]      = k1 * cs - k2 * sn;
    g_k[o + i + 32] = k2 * cs + k1 * sn;
    g_v[o + i]      = v1;
    g_v[o + i + 32] = v2;
}

// ============================================================
// Flash attention (fp32 SIMT, unchanged)
// ============================================================
#define TJ 16

__global__ __launch_bounds__(128) void attn_kernel()
{
    const int bh = blockIdx.y;
    const int qt = blockIdx.x;
    const int t  = threadIdx.x;
    const int row = qt * 128 + t;

    __shared__ float Ks[TJ * Dn];
    __shared__ float Vs[TJ * Dn];

    const float* qptr = g_q + ((size_t)bh * Sn + row) * Dn;
    float q[Dn];
    #pragma unroll
    for (int i = 0; i < 16; i++) {
        float4 v = *(const float4*)(qptr + i * 4);
        q[4*i] = v.x; q[4*i+1] = v.y; q[4*i+2] = v.z; q[4*i+3] = v.w;
    }

    float o[Dn];
    #pragma unroll
    for (int d = 0; d < Dn; d++) o[d] = 0.f;
    float m = -1e30f, l = 0.f;
    const float scale = 0.125f;

    for (int j0 = 0; j0 < Sn; j0 += TJ) {
        const float4* kt = (const float4*)(g_k + ((size_t)bh * Sn + j0) * Dn);
        const float4* vt = (const float4*)(g_v + ((size_t)bh * Sn + j0) * Dn);
        __syncthreads();
        #pragma unroll
        for (int i = 0; i < (TJ * Dn / 4) / 128; i++) {
            int idx = t + i * 128;
            ((float4*)Ks)[idx] = kt[idx];
            ((float4*)Vs)[idx] = vt[idx];
        }
        __syncthreads();

        float s[TJ];
        float mt = m;
        #pragma unroll
        for (int j = 0; j < TJ; j++) {
            float acc2 = 0.f;
            const float4* krow = (const float4*)(Ks + j * Dn);
            #pragma unroll
            for (int d4 = 0; d4 < 16; d4++) {
                float4 kv = krow[d4];
                acc2 = fmaf(q[4*d4+0], kv.x, acc2);
                acc2 = fmaf(q[4*d4+1], kv.y, acc2);
                acc2 = fmaf(q[4*d4+2], kv.z, acc2);
                acc2 = fmaf(q[4*d4+3], kv.w, acc2);
            }
            s[j] = acc2 * scale;
            mt = fmaxf(mt, s[j]);
        }

        float corr = __expf(m - mt);
        m = mt;
        l *= corr;
        #pragma unroll
        for (int d = 0; d < Dn; d++) o[d] *= corr;

        #pragma unroll
        for (int j = 0; j < TJ; j++) {
            float p = __expf(s[j] - m);
            l += p;
            const float4* vrow = (const float4*)(Vs + j * Dn);
            #pragma unroll
            for (int d4 = 0; d4 < 16; d4++) {
                float4 vv = vrow[d4];
                o[4*d4+0] = fmaf(p, vv.x, o[4*d4+0]);
                o[4*d4+1] = fmaf(p, vv.y, o[4*d4+1]);
                o[4*d4+2] = fmaf(p, vv.z, o[4*d4+2]);
                o[4*d4+3] = fmaf(p, vv.w, o[4*d4+3]);
            }
        }
    }

    float inv_l = 1.f / l;
    int b = bh >> 4, h = bh & 15;
    float* optr = g_att + (size_t)(b * Sn + row) * Cn + h * Dn;
    #pragma unroll
    for (int i = 0; i < 16; i++) {
        float4 v;
        v.x = o[4*i+0] * inv_l;
        v.y = o[4*i+1] * inv_l;
        v.z = o[4*i+2] * inv_l;
        v.w = o[4*i+3] * inv_l;
        *(float4*)(optr + 4 * i) = v;
    }
}

// ============================================================
// Launch
// ============================================================
extern "C" void kernel_launch(void* const* d_in, const int* in_sizes, int n_in,
                              void* d_out, int out_size)
{
    const float* x      = (const float*)d_in[0];
    const float* W_qkv  = (const float*)d_in[1];
    const float* b_qkv  = (const float*)d_in[2];
    const float* W_proj = (const float*)d_in[3];
    const float* b_proj = (const float*)d_in[4];
    float* out = (float*)d_out;

    cudaFuncSetAttribute(gemm_mma, cudaFuncAttributeMaxDynamicSharedMemorySize, GM_SMEM);

    float *p_qkv, *p_att;
    __nv_bfloat16 *p_A3, *p_B3;
    cudaGetSymbolAddress((void**)&p_qkv, g_qkv);
    cudaGetSymbolAddress((void**)&p_att, g_att);
    cudaGetSymbolAddress((void**)&p_A3, g_A3);
    cudaGetSymbolAddress((void**)&p_B3, g_B3);

    // 1) split-convert x and W_qkv
    conv_A<<<(Mn * Cn) / 256, 256>>>(x, p_A3, Cn);
    {
        dim3 g(Cn / 32, N1 / 32);
        conv_B<<<g, 256>>>(W_qkv, p_B3, Cn, N1);
    }
    // 2) QKV GEMM (HMMA): g_qkv = x @ W_qkv + b_qkv
    {
        dim3 g(N1 / 128, Mn / 128);
        gemm_mma<<<g, 256, GM_SMEM>>>(p_A3, p_B3, b_qkv, p_qkv, N1, KP);
    }
    // 3) RoPE + transpose
    rope_scatter_kernel<<<(Bn * Hn * Sn * 32) / 256, 256>>>();
    // 4) Flash attention -> g_att
    {
        dim3 g(Sn / 128, Bn * Hn);
        attn_kernel<<<g, 128>>>();
    }
    // 5) split-convert g_att and W_proj
    conv_A<<<(Mn * Cn) / 256, 256>>>(p_att, p_A3, Cn);
    {
        dim3 g(Cn / 32, Cn / 32);
        conv_B<<<g, 256>>>(W_proj, p_B3, Cn, Cn);
    }
    // 6) output projection (HMMA)
    {
        dim3 g(Cn / 128, Mn / 128);
        gemm_mma<<<g, 256, GM_SMEM>>>(p_A3, p_B3, b_proj, out, Cn, KP);
    }
}

// round 4
// speedup vs baseline: 2.8201x; 2.0881x over previous
#include <cuda_runtime.h>
#include <cuda_bf16.h>
#include <math.h>
#include <cstdint>

#define Bn 8
#define Sn 1024
#define Cn 1024
#define Hn 16
#define Dn 64
#define Mn (Bn*Sn)        // 8192
#define N1 (3*Cn)         // 3072
#define KP (3*Cn)         // extended K for hi/lo-split GEMM

// ---- scratch (static device globals; no allocation) ----
__device__ float g_qkv[(size_t)Mn * N1];            // (B,S,3C)
__device__ __nv_bfloat16 g_qh[(size_t)Bn*Hn*Sn*Dn]; // split q/k/v (B,H,S,D)
__device__ __nv_bfloat16 g_ql[(size_t)Bn*Hn*Sn*Dn];
__device__ __nv_bfloat16 g_kh[(size_t)Bn*Hn*Sn*Dn];
__device__ __nv_bfloat16 g_kl[(size_t)Bn*Hn*Sn*Dn];
__device__ __nv_bfloat16 g_vh[(size_t)Bn*Hn*Sn*Dn];
__device__ __nv_bfloat16 g_vl[(size_t)Bn*Hn*Sn*Dn];
__device__ __nv_bfloat16 g_A3[(size_t)Mn * KP];     // split A for GEMMs
__device__ __nv_bfloat16 g_B3[(size_t)N1 * KP];     // split B^T for GEMMs

// ============================================================
// helpers
// ============================================================
__device__ __forceinline__ uint32_t smem_u32(const void* p) {
    uint32_t a;
    asm("{ .reg .u64 t; cvta.to.shared.u64 t, %1; cvt.u32.u64 %0, t; }"
        : "=r"(a) : "l"(p));
    return a;
}
__device__ __forceinline__ void cpa16(uint32_t s, const void* g) {
    asm volatile("cp.async.cg.shared.global [%0], [%1], 16;" :: "r"(s), "l"(g));
}
__device__ __forceinline__ void ldm4(uint32_t addr, uint32_t& r0, uint32_t& r1,
                                     uint32_t& r2, uint32_t& r3) {
    asm volatile("ldmatrix.sync.aligned.m8n8.x4.shared.b16 {%0,%1,%2,%3}, [%4];"
                 : "=r"(r0), "=r"(r1), "=r"(r2), "=r"(r3) : "r"(addr));
}
__device__ __forceinline__ void ldm4t(uint32_t addr, uint32_t& r0, uint32_t& r1,
                                      uint32_t& r2, uint32_t& r3) {
    asm volatile("ldmatrix.sync.aligned.m8n8.x4.trans.shared.b16 {%0,%1,%2,%3}, [%4];"
                 : "=r"(r0), "=r"(r1), "=r"(r2), "=r"(r3) : "r"(addr));
}
__device__ __forceinline__ void mma_bf16(float* d, const uint32_t* a,
                                         uint32_t b0, uint32_t b1) {
    asm volatile(
        "mma.sync.aligned.m16n8k16.row.col.f32.bf16.bf16.f32 "
        "{%0,%1,%2,%3}, {%4,%5,%6,%7}, {%8,%9}, {%0,%1,%2,%3};"
        : "+f"(d[0]), "+f"(d[1]), "+f"(d[2]), "+f"(d[3])
        : "r"(a[0]), "r"(a[1]), "r"(a[2]), "r"(a[3]), "r"(b0), "r"(b1));
}
__device__ __forceinline__ float ex2(float x) {
    float r;
    asm("ex2.approx.f32 %0, %1;" : "=f"(r) : "f"(x));
    return r;
}
__device__ __forceinline__ void split2(float v, __nv_bfloat16& h, __nv_bfloat16& l) {
    h = __float2bfloat16(v);
    l = __float2bfloat16(v - __bfloat162float(h));
}
__device__ __forceinline__ uint32_t packbf(__nv_bfloat16 a, __nv_bfloat16 b) {
    __nv_bfloat162 t(a, b);   // a -> low half (k even), b -> high half
    return *(uint32_t*)&t;
}

// ============================================================
// Split conversions for the dense GEMMs
// A3 = [hi | lo | hi], B3 = [hi | hi | lo]  (K'=3K)
// ============================================================
__global__ __launch_bounds__(256) void conv_A(const float* __restrict__ A,
                                              __nv_bfloat16* __restrict__ A3, int Kdim)
{
    int idx = blockIdx.x * 256 + threadIdx.x;
    int r = idx / Kdim, k = idx - r * Kdim;
    float v = A[idx];
    __nv_bfloat16 hi, lo;
    split2(v, hi, lo);
    size_t base = (size_t)r * (3 * Kdim);
    A3[base + k] = hi;
    A3[base + Kdim + k] = lo;
    A3[base + 2 * Kdim + k] = hi;
}

__global__ __launch_bounds__(256) void conv_B(const float* __restrict__ W,
                                              __nv_bfloat16* __restrict__ B3,
                                              int Kdim, int Ndim)
{
    __shared__ float t[32][33];
    int k0 = blockIdx.x * 32, n0 = blockIdx.y * 32;
    int tx = threadIdx.x & 31, ty = threadIdx.x >> 5;
    #pragma unroll
    for (int i = 0; i < 4; i++)
        t[ty + i * 8][tx] = W[(size_t)(k0 + ty + i * 8) * Ndim + n0 + tx];
    __syncthreads();
    #pragma unroll
    for (int i = 0; i < 4; i++) {
        int n = ty + i * 8;
        float v = t[tx][n];
        __nv_bfloat16 hi, lo;
        split2(v, hi, lo);
        size_t base = (size_t)(n0 + n) * (3 * Kdim);
        B3[base + k0 + tx] = hi;
        B3[base + Kdim + k0 + tx] = hi;
        B3[base + 2 * Kdim + k0 + tx] = lo;
    }
}

// ============================================================
// HMMA bf16 GEMM (unchanged from round 3)
// ============================================================
#define KT 64
#define ROWB 144
#define TILEB (128 * ROWB)
#define GM_SMEM (4 * TILEB)

__global__ __launch_bounds__(256) void gemm_mma(
    const __nv_bfloat16* __restrict__ A, const __nv_bfloat16* __restrict__ B,
    const float* __restrict__ bias, float* __restrict__ C,
    int Ndim, int Kp)
{
    extern __shared__ char smraw[];
    const uint32_t sb = smem_u32(smraw);
    const int tid = threadIdx.x;
    const int wid = tid >> 5, lane = tid & 31;
    const int brow = blockIdx.y * 128, bcol = blockIdx.x * 128;
    const int warpM = (wid >> 2) * 64;
    const int warpN = (wid & 3) * 32;

    float acc[4][4][4];
    #pragma unroll
    for (int i = 0; i < 4; i++)
        #pragma unroll
        for (int j = 0; j < 4; j++)
            #pragma unroll
            for (int e = 0; e < 4; e++) acc[i][j][e] = 0.f;

    const int NT = Kp / KT;

    auto load_tile = [&](int kc, int buf) {
        uint32_t ab = sb + buf * (2 * TILEB);
        uint32_t bb = ab + TILEB;
        const __nv_bfloat16* Ag = A + (size_t)brow * Kp + kc * KT;
        const __nv_bfloat16* Bg = B + (size_t)bcol * Kp + kc * KT;
        #pragma unroll
        for (int i = 0; i < 4; i++) {
            int slot = i * 256 + tid;
            int r = slot >> 3, c = slot & 7;
            uint32_t so = (uint32_t)(r * ROWB + c * 16);
            cpa16(ab + so, Ag + (size_t)r * Kp + c * 8);
            cpa16(bb + so, Bg + (size_t)r * Kp + c * 8);
        }
        asm volatile("cp.async.commit_group;" ::: "memory");
    };

    load_tile(0, 0);

    const int lm = lane & 15, lh = lane >> 4;

    for (int kt = 0; kt < NT; kt++) {
        int cur = kt & 1;
        if (kt + 1 < NT) load_tile(kt + 1, cur ^ 1);

        if (kt + 1 < NT)
            asm volatile("cp.async.wait_group 1;" ::: "memory");
        else
            asm volatile("cp.async.wait_group 0;" ::: "memory");
        __syncthreads();

        uint32_t ab = sb + cur * (2 * TILEB);
        uint32_t bb = ab + TILEB;
        uint32_t aAddr = ab + (uint32_t)((warpM + lm) * ROWB + lh * 16);
        uint32_t bAddr = bb + (uint32_t)((warpN + lm) * ROWB + lh * 16);

        #pragma unroll
        for (int ks = 0; ks < 4; ks++) {
            uint32_t afr[4][4];
            #pragma unroll
            for (int mf = 0; mf < 4; mf++)
                ldm4(aAddr + mf * 16 * ROWB + ks * 32,
                     afr[mf][0], afr[mf][1], afr[mf][2], afr[mf][3]);
            uint32_t bfr[4][2];
            #pragma unroll
            for (int nb = 0; nb < 2; nb++) {
                uint32_t r0, r1, r2, r3;
                ldm4(bAddr + nb * 16 * ROWB + ks * 32, r0, r1, r2, r3);
                bfr[nb * 2 + 0][0] = r0; bfr[nb * 2 + 0][1] = r2;
                bfr[nb * 2 + 1][0] = r1; bfr[nb * 2 + 1][1] = r3;
            }
            #pragma unroll
            for (int mf = 0; mf < 4; mf++)
                #pragma unroll
                for (int nf = 0; nf < 4; nf++)
                    mma_bf16(acc[mf][nf], afr[mf], bfr[nf][0], bfr[nf][1]);
        }
        __syncthreads();
    }

    #pragma unroll
    for (int mf = 0; mf < 4; mf++) {
        int grow = brow + warpM + mf * 16 + (lane >> 2);
        #pragma unroll
        for (int nf = 0; nf < 4; nf++) {
            int gcol = bcol + warpN + nf * 8 + (lane & 3) * 2;
            float bx = bias[gcol], by = bias[gcol + 1];
            float* d = acc[mf][nf];
            float2 v0 = {d[0] + bx, d[1] + by};
            float2 v1 = {d[2] + bx, d[3] + by};
            *(float2*)&C[(size_t)grow * Ndim + gcol] = v0;
            *(float2*)&C[(size_t)(grow + 8) * Ndim + gcol] = v1;
        }
    }
}

// ============================================================
// RoPE + hi/lo split scatter:
// q scaled by 0.125*log2(e) (softmax done in exp2 domain).
// ============================================================
__global__ __launch_bounds__(256) void rope_split_kernel()
{
    int idx = blockIdx.x * blockDim.x + threadIdx.x;
    int i = idx & 31;
    int s = (idx >> 5)  & (Sn - 1);
    int h = (idx >> 15) & (Hn - 1);
    int b =  idx >> 19;

    const float* row = g_qkv + (size_t)(b * Sn + s) * N1;
    int base = h * Dn;

    float inv = expf(-(logf(10000.f) / Dn) * (2.f * i));
    float ang = (float)s * inv;
    float sn, cs;
    sincosf(ang, &sn, &cs);

    float q1 = row[0*Cn + base + i];
    float q2 = row[0*Cn + base + i + 32];
    float k1 = row[1*Cn + base + i];
    float k2 = row[1*Cn + base + i + 32];
    float v1 = row[2*Cn + base + i];
    float v2 = row[2*Cn + base + i + 32];

    const float QS = 0.18033688011112042f;  // 0.125 * log2(e)

    float qa = (q1 * cs - q2 * sn) * QS;
    float qb = (q2 * cs + q1 * sn) * QS;
    float ka = k1 * cs - k2 * sn;
    float kb = k2 * cs + k1 * sn;

    size_t o = ((size_t)(b * Hn + h) * Sn + s) * Dn;
    __nv_bfloat16 hh, ll;
    split2(qa, hh, ll); g_qh[o + i] = hh;      g_ql[o + i] = ll;
    split2(qb, hh, ll); g_qh[o + i + 32] = hh; g_ql[o + i + 32] = ll;
    split2(ka, hh, ll); g_kh[o + i] = hh;      g_kl[o + i] = ll;
    split2(kb, hh, ll); g_kh[o + i + 32] = hh; g_kl[o + i + 32] = ll;
    split2(v1, hh, ll); g_vh[o + i] = hh;      g_vl[o + i] = ll;
    split2(v2, hh, ll); g_vh[o + i + 32] = hh; g_vl[o + i + 32] = ll;
}

// ============================================================
// HMMA flash attention with 3-product hi/lo splits.
// CTA: 8 warps, 128 q-rows, key tiles of 128, double-buffered K/V.
// Writes O directly as split A3 rows for the proj GEMM.
// ============================================================
#define AT_ROWB 144
#define AT_TILE (128 * AT_ROWB)            // 18432 per array
#define AT_STAGE (4 * AT_TILE)             // khi,klo,vhi,vlo
#define AT_SMEM (2 * AT_TILE + 2 * AT_STAGE)  // Q(hi,lo) + 2 stages = 184320

__global__ __launch_bounds__(256, 1) void attn_mma()
{
    extern __shared__ char smraw[];
    const uint32_t sb = smem_u32(smraw);
    const int tid = threadIdx.x, wid = tid >> 5, lane = tid & 31;
    const int bh = blockIdx.y;
    const int q0 = blockIdx.x * 128;
    const size_t bhoff = (size_t)bh * Sn * Dn;

    const uint32_t qhi_s = sb;
    const uint32_t qlo_s = sb + AT_TILE;
    const uint32_t stage0 = sb + 2 * AT_TILE;

    // ---- load Q (hi,lo) tile: 128 x 64 bf16 each ----
    {
        const __nv_bfloat16* Qh = g_qh + bhoff + (size_t)q0 * Dn;
        const __nv_bfloat16* Ql = g_ql + bhoff + (size_t)q0 * Dn;
        #pragma unroll
        for (int i = 0; i < 4; i++) {
            int slot = i * 256 + tid;        // 0..1023
            int r = slot >> 3, c = slot & 7;
            uint32_t so = (uint32_t)(r * AT_ROWB + c * 16);
            cpa16(qhi_s + so, Qh + (size_t)r * Dn + c * 8);
            cpa16(qlo_s + so, Ql + (size_t)r * Dn + c * 8);
        }
    }
    // ---- stage 0 K/V ----
    auto load_kv = [&](int t, int buf) {
        uint32_t st = stage0 + buf * AT_STAGE;
        const __nv_bfloat16* Kh = g_kh + bhoff + (size_t)t * 128 * Dn;
        const __nv_bfloat16* Kl = g_kl + bhoff + (size_t)t * 128 * Dn;
        const __nv_bfloat16* Vh = g_vh + bhoff + (size_t)t * 128 * Dn;
        const __nv_bfloat16* Vl = g_vl + bhoff + (size_t)t * 128 * Dn;
        #pragma unroll
        for (int i = 0; i < 4; i++) {
            int slot = i * 256 + tid;
            int r = slot >> 3, c = slot & 7;
            uint32_t so = (uint32_t)(r * AT_ROWB + c * 16);
            size_t go = (size_t)r * Dn + c * 8;
            cpa16(st + so, Kh + go);
            cpa16(st + AT_TILE + so, Kl + go);
            cpa16(st + 2 * AT_TILE + so, Vh + go);
            cpa16(st + 3 * AT_TILE + so, Vl + go);
        }
        asm volatile("cp.async.commit_group;" ::: "memory");
    };
    load_kv(0, 0);

    asm volatile("cp.async.wait_group 0;" ::: "memory");
    __syncthreads();

    // ---- Q fragments (persist in registers) ----
    const int lm = lane & 15, lh = lane >> 4;
    uint32_t qh[4][4], ql[4][4];
    {
        uint32_t a = (uint32_t)((wid * 16 + lm) * AT_ROWB + lh * 16);
        #pragma unroll
        for (int ks = 0; ks < 4; ks++) {
            ldm4(qhi_s + a + ks * 32, qh[ks][0], qh[ks][1], qh[ks][2], qh[ks][3]);
            ldm4(qlo_s + a + ks * 32, ql[ks][0], ql[ks][1], ql[ks][2], ql[ks][3]);
        }
    }

    float o[8][4];
    #pragma unroll
    for (int i = 0; i < 8; i++)
        #pragma unroll
        for (int e = 0; e < 4; e++) o[i][e] = 0.f;
    float m0 = -1e30f, m1 = -1e30f, ps0 = 0.f, ps1 = 0.f;

    for (int t = 0; t < 8; t++) {
        if (t > 0) {
            asm volatile("cp.async.wait_group 0;" ::: "memory");
            __syncthreads();
        }
        if (t < 7) load_kv(t + 1, (t + 1) & 1);

        uint32_t st = stage0 + (t & 1) * AT_STAGE;
        uint32_t kh_s = st, kl_s = st + AT_TILE;
        uint32_t vh_s = st + 2 * AT_TILE, vl_s = st + 3 * AT_TILE;

        // ---- QK^T: sc = qhi*khi + qlo*khi + qhi*klo ----
        float sc[16][4];
        #pragma unroll
        for (int f = 0; f < 16; f++)
            #pragma unroll
            for (int e = 0; e < 4; e++) sc[f][e] = 0.f;

        uint32_t bbase = (uint32_t)(lm * AT_ROWB + lh * 16);
        #pragma unroll
        for (int nb = 0; nb < 8; nb++) {
            uint32_t ah = kh_s + bbase + nb * 16 * AT_ROWB;
            uint32_t al = kl_s + bbase + nb * 16 * AT_ROWB;
            #pragma unroll
            for (int ks = 0; ks < 4; ks++) {
                uint32_t h0, h1, h2, h3, l0, l1, l2, l3;
                ldm4(ah + ks * 32, h0, h1, h2, h3);
                ldm4(al + ks * 32, l0, l1, l2, l3);
                mma_bf16(sc[2 * nb],     qh[ks], h0, h2);
                mma_bf16(sc[2 * nb],     ql[ks], h0, h2);
                mma_bf16(sc[2 * nb],     qh[ks], l0, l2);
                mma_bf16(sc[2 * nb + 1], qh[ks], h1, h3);
                mma_bf16(sc[2 * nb + 1], ql[ks], h1, h3);
                mma_bf16(sc[2 * nb + 1], qh[ks], l1, l3);
            }
        }

        // ---- online softmax (exp2 domain; scale folded into q) ----
        float mx0 = -1e30f, mx1 = -1e30f;
        #pragma unroll
        for (int f = 0; f < 16; f++) {
            mx0 = fmaxf(mx0, fmaxf(sc[f][0], sc[f][1]));
            mx1 = fmaxf(mx1, fmaxf(sc[f][2], sc[f][3]));
        }
        mx0 = fmaxf(mx0, __shfl_xor_sync(0xffffffffu, mx0, 1));
        mx0 = fmaxf(mx0, __shfl_xor_sync(0xffffffffu, mx0, 2));
        mx1 = fmaxf(mx1, __shfl_xor_sync(0xffffffffu, mx1, 1));
        mx1 = fmaxf(mx1, __shfl_xor_sync(0xffffffffu, mx1, 2));

        float mn0 = fmaxf(m0, mx0), mn1 = fmaxf(m1, mx1);
        float f0 = ex2(m0 - mn0), f1 = ex2(m1 - mn1);
        m0 = mn0; m1 = mn1;
        ps0 *= f0; ps1 *= f1;
        #pragma unroll
        for (int nf = 0; nf < 8; nf++) {
            o[nf][0] *= f0; o[nf][1] *= f0;
            o[nf][2] *= f1; o[nf][3] *= f1;
        }

        // ---- p = exp2(sc - m), split to bf16 hi/lo A-fragments ----
        uint32_t pa_hi[8][4], pa_lo[8][4];
        #pragma unroll
        for (int t2 = 0; t2 < 8; t2++) {
            #pragma unroll
            for (int half = 0; half < 2; half++) {
                int f = 2 * t2 + half;
                float p0 = ex2(sc[f][0] - m0);
                float p1 = ex2(sc[f][1] - m0);
                float p2 = ex2(sc[f][2] - m1);
                float p3 = ex2(sc[f][3] - m1);
                ps0 += p0 + p1; ps1 += p2 + p3;
                __nv_bfloat16 h0, l0, h1, l1, h2, l2, h3, l3;
                split2(p0, h0, l0); split2(p1, h1, l1);
                split2(p2, h2, l2); split2(p3, h3, l3);
                pa_hi[t2][half * 2 + 0] = packbf(h0, h1);
                pa_hi[t2][half * 2 + 1] = packbf(h2, h3);
                pa_lo[t2][half * 2 + 0] = packbf(l0, l1);
                pa_lo[t2][half * 2 + 1] = packbf(l2, l3);
            }
        }

        // ---- PV: o += phi*vhi + plo*vhi + phi*vlo ----
        #pragma unroll
        for (int t2 = 0; t2 < 8; t2++) {
            uint32_t vrow = (uint32_t)((t2 * 16 + lm) * AT_ROWB + lh * 16);
            #pragma unroll
            for (int dn = 0; dn < 4; dn++) {
                uint32_t h0, h1, h2, h3, l0, l1, l2, l3;
                ldm4t(vh_s + vrow + dn * 32, h0, h1, h2, h3);
                ldm4t(vl_s + vrow + dn * 32, l0, l1, l2, l3);
                mma_bf16(o[2 * dn],     pa_hi[t2], h0, h1);
                mma_bf16(o[2 * dn],     pa_lo[t2], h0, h1);
                mma_bf16(o[2 * dn],     pa_hi[t2], l0, l1);
                mma_bf16(o[2 * dn + 1], pa_hi[t2], h2, h3);
                mma_bf16(o[2 * dn + 1], pa_lo[t2], h2, h3);
                mma_bf16(o[2 * dn + 1], pa_hi[t2], l2, l3);
            }
        }
        __syncthreads();   // all warps done reading this stage before reuse
    }

    // ---- finalize: row sums, divide, write split A3 rows ----
    ps0 += __shfl_xor_sync(0xffffffffu, ps0, 1);
    ps0 += __shfl_xor_sync(0xffffffffu, ps0, 2);
    ps1 += __shfl_xor_sync(0xffffffffu, ps1, 1);
    ps1 += __shfl_xor_sync(0xffffffffu, ps1, 2);
    float inv0 = 1.f / ps0, inv1 = 1.f / ps1;

    const int bidx = bh >> 4, hidx = bh & 15;
    const int grow = bidx * Sn + q0 + wid * 16 + (lane >> 2);

    #pragma unroll
    for (int nf = 0; nf < 8; nf++) {
        int col = hidx * 64 + nf * 8 + (lane & 3) * 2;
        float v0 = o[nf][0] * inv0, v1 = o[nf][1] * inv0;
        float v2 = o[nf][2] * inv1, v3 = o[nf][3] * inv1;
        __nv_bfloat16 h0, l0, h1, l1, h2, l2, h3, l3;
        split2(v0, h0, l0); split2(v1, h1, l1);
        split2(v2, h2, l2); split2(v3, h3, l3);
        uint32_t hp0 = packbf(h0, h1), lp0 = packbf(l0, l1);
        uint32_t hp1 = packbf(h2, h3), lp1 = packbf(l2, l3);
        size_t r0 = (size_t)grow * KP + col;
        size_t r1 = (size_t)(grow + 8) * KP + col;
        *(uint32_t*)&g_A3[r0]        = hp0;
        *(uint32_t*)&g_A3[r0 + 1024] = lp0;
        *(uint32_t*)&g_A3[r0 + 2048] = hp0;
        *(uint32_t*)&g_A3[r1]        = hp1;
        *(uint32_t*)&g_A3[r1 + 1024] = lp1;
        *(uint32_t*)&g_A3[r1 + 2048] = hp1;
    }
}

// ============================================================
// Launch
// ============================================================
extern "C" void kernel_launch(void* const* d_in, const int* in_sizes, int n_in,
                              void* d_out, int out_size)
{
    const float* x      = (const float*)d_in[0];
    const float* W_qkv  = (const float*)d_in[1];
    const float* b_qkv  = (const float*)d_in[2];
    const float* W_proj = (const float*)d_in[3];
    const float* b_proj = (const float*)d_in[4];
    float* out = (float*)d_out;

    cudaFuncSetAttribute(gemm_mma, cudaFuncAttributeMaxDynamicSharedMemorySize, GM_SMEM);
    cudaFuncSetAttribute(attn_mma, cudaFuncAttributeMaxDynamicSharedMemorySize, AT_SMEM);

    float* p_qkv;
    __nv_bfloat16 *p_A3, *p_B3;
    cudaGetSymbolAddress((void**)&p_qkv, g_qkv);
    cudaGetSymbolAddress((void**)&p_A3, g_A3);
    cudaGetSymbolAddress((void**)&p_B3, g_B3);

    // 1) split-convert x and W_qkv
    conv_A<<<(Mn * Cn) / 256, 256>>>(x, p_A3, Cn);
    {
        dim3 g(Cn / 32, N1 / 32);
        conv_B<<<g, 256>>>(W_qkv, p_B3, Cn, N1);
    }
    // 2) QKV GEMM (HMMA)
    {
        dim3 g(N1 / 128, Mn / 128);
        gemm_mma<<<g, 256, GM_SMEM>>>(p_A3, p_B3, b_qkv, p_qkv, N1, KP);
    }
    // 3) RoPE + hi/lo split
    rope_split_kernel<<<(Bn * Hn * Sn * 32) / 256, 256>>>();
    // 4) HMMA flash attention -> writes split A3 directly
    {
        dim3 g(Sn / 128, Bn * Hn);
        attn_mma<<<g, 256, AT_SMEM>>>();
    }
    // 5) split-convert W_proj only (A3 already written by attention)
    {
        dim3 g(Cn / 32, Cn / 32);
        conv_B<<<g, 256>>>(W_proj, p_B3, Cn, Cn);
    }
    // 6) output projection (HMMA)
    {
        dim3 g(Cn / 128, Mn / 128);
        gemm_mma<<<g, 256, GM_SMEM>>>(p_A3, p_B3, b_proj, out, Cn, KP);
    }
}

// round 5
// speedup vs baseline: 2.8607x; 1.0144x over previous
#include <cuda_runtime.h>
#include <cuda_bf16.h>
#include <math.h>
#include <cstdint>

#define Bn 8
#define Sn 1024
#define Cn 1024
#define Hn 16
#define Dn 64
#define Mn (Bn*Sn)        // 8192
#define N1 (3*Cn)         // 3072
#define KP (3*Cn)         // extended K for hi/lo-split GEMM

// ---- scratch (static device globals; no allocation) ----
__device__ float g_qkv[(size_t)Mn * N1];            // (B,S,3C)
__device__ __nv_bfloat16 g_qh[(size_t)Bn*Hn*Sn*Dn]; // split q/k/v (B,H,S,D)
__device__ __nv_bfloat16 g_ql[(size_t)Bn*Hn*Sn*Dn];
__device__ __nv_bfloat16 g_kh[(size_t)Bn*Hn*Sn*Dn];
__device__ __nv_bfloat16 g_kl[(size_t)Bn*Hn*Sn*Dn];
__device__ __nv_bfloat16 g_vh[(size_t)Bn*Hn*Sn*Dn];
__device__ __nv_bfloat16 g_vl[(size_t)Bn*Hn*Sn*Dn];
__device__ __nv_bfloat16 g_A3[(size_t)Mn * KP];     // split A for GEMMs
__device__ __nv_bfloat16 g_B3[(size_t)N1 * KP];     // split B^T for GEMMs

// ============================================================
// helpers
// ============================================================
__device__ __forceinline__ uint32_t smem_u32(const void* p) {
    uint32_t a;
    asm("{ .reg .u64 t; cvta.to.shared.u64 t, %1; cvt.u32.u64 %0, t; }"
        : "=r"(a) : "l"(p));
    return a;
}
__device__ __forceinline__ void cpa16(uint32_t s, const void* g) {
    asm volatile("cp.async.cg.shared.global [%0], [%1], 16;" :: "r"(s), "l"(g));
}
__device__ __forceinline__ void ldm4(uint32_t addr, uint32_t& r0, uint32_t& r1,
                                     uint32_t& r2, uint32_t& r3) {
    asm volatile("ldmatrix.sync.aligned.m8n8.x4.shared.b16 {%0,%1,%2,%3}, [%4];"
                 : "=r"(r0), "=r"(r1), "=r"(r2), "=r"(r3) : "r"(addr));
}
__device__ __forceinline__ void ldm4t(uint32_t addr, uint32_t& r0, uint32_t& r1,
                                      uint32_t& r2, uint32_t& r3) {
    asm volatile("ldmatrix.sync.aligned.m8n8.x4.trans.shared.b16 {%0,%1,%2,%3}, [%4];"
                 : "=r"(r0), "=r"(r1), "=r"(r2), "=r"(r3) : "r"(addr));
}
__device__ __forceinline__ void mma_bf16(float* d, const uint32_t* a,
                                         uint32_t b0, uint32_t b1) {
    asm volatile(
        "mma.sync.aligned.m16n8k16.row.col.f32.bf16.bf16.f32 "
        "{%0,%1,%2,%3}, {%4,%5,%6,%7}, {%8,%9}, {%0,%1,%2,%3};"
        : "+f"(d[0]), "+f"(d[1]), "+f"(d[2]), "+f"(d[3])
        : "r"(a[0]), "r"(a[1]), "r"(a[2]), "r"(a[3]), "r"(b0), "r"(b1));
}
__device__ __forceinline__ float ex2(float x) {
    float r;
    asm("ex2.approx.f32 %0, %1;" : "=f"(r) : "f"(x));
    return r;
}
__device__ __forceinline__ void split2(float v, __nv_bfloat16& h, __nv_bfloat16& l) {
    h = __float2bfloat16(v);
    l = __float2bfloat16(v - __bfloat162float(h));
}
__device__ __forceinline__ uint32_t packbf(__nv_bfloat16 a, __nv_bfloat16 b) {
    __nv_bfloat162 t(a, b);
    return *(uint32_t*)&t;
}

// ============================================================
// Split conversions for the dense GEMMs
// A3 = [hi | lo | hi], B3 = [hi | hi | lo]  (K'=3K)
// ============================================================
__global__ __launch_bounds__(256) void conv_A(const float* __restrict__ A,
                                              __nv_bfloat16* __restrict__ A3, int Kdim)
{
    int idx = blockIdx.x * 256 + threadIdx.x;
    int r = idx / Kdim, k = idx - r * Kdim;
    float v = A[idx];
    __nv_bfloat16 hi, lo;
    split2(v, hi, lo);
    size_t base = (size_t)r * (3 * Kdim);
    A3[base + k] = hi;
    A3[base + Kdim + k] = lo;
    A3[base + 2 * Kdim + k] = hi;
}

__global__ __launch_bounds__(256) void conv_B(const float* __restrict__ W,
                                              __nv_bfloat16* __restrict__ B3,
                                              int Kdim, int Ndim)
{
    __shared__ float t[32][33];
    int k0 = blockIdx.x * 32, n0 = blockIdx.y * 32;
    int tx = threadIdx.x & 31, ty = threadIdx.x >> 5;
    #pragma unroll
    for (int i = 0; i < 4; i++)
        t[ty + i * 8][tx] = W[(size_t)(k0 + ty + i * 8) * Ndim + n0 + tx];
    __syncthreads();
    #pragma unroll
    for (int i = 0; i < 4; i++) {
        int n = ty + i * 8;
        float v = t[tx][n];
        __nv_bfloat16 hi, lo;
        split2(v, hi, lo);
        size_t base = (size_t)(n0 + n) * (3 * Kdim);
        B3[base + k0 + tx] = hi;
        B3[base + Kdim + k0 + tx] = hi;
        B3[base + 2 * Kdim + k0 + tx] = lo;
    }
}

// ============================================================
// HMMA bf16 GEMM: 3-stage cp.async pipeline, single sync/iter.
// 128x128 CTA tile, K-tile 64, 8 warps, warp tile 64x32.
// ============================================================
#define KT 64
#define ROWB 144
#define TILEB (128 * ROWB)
#define NSTG 3
#define GM_SMEM (NSTG * 2 * TILEB)     // 110592 B -> 2 CTAs/SM

__global__ __launch_bounds__(256, 2) void gemm_mma(
    const __nv_bfloat16* __restrict__ A, const __nv_bfloat16* __restrict__ B,
    const float* __restrict__ bias, float* __restrict__ C,
    int Ndim, int Kp)
{
    extern __shared__ char smraw[];
    const uint32_t sb = smem_u32(smraw);
    const int tid = threadIdx.x;
    const int wid = tid >> 5, lane = tid & 31;
    const int brow = blockIdx.y * 128, bcol = blockIdx.x * 128;
    const int warpM = (wid >> 2) * 64;
    const int warpN = (wid & 3) * 32;

    float acc[4][4][4];
    #pragma unroll
    for (int i = 0; i < 4; i++)
        #pragma unroll
        for (int j = 0; j < 4; j++)
            #pragma unroll
            for (int e = 0; e < 4; e++) acc[i][j][e] = 0.f;

    const int NT = Kp / KT;

    auto load_tile = [&](int kc, int buf) {
        uint32_t ab = sb + buf * (2 * TILEB);
        uint32_t bb = ab + TILEB;
        const __nv_bfloat16* Ag = A + (size_t)brow * Kp + kc * KT;
        const __nv_bfloat16* Bg = B + (size_t)bcol * Kp + kc * KT;
        #pragma unroll
        for (int i = 0; i < 4; i++) {
            int slot = i * 256 + tid;
            int r = slot >> 3, c = slot & 7;
            uint32_t so = (uint32_t)(r * ROWB + c * 16);
            cpa16(ab + so, Ag + (size_t)r * Kp + c * 8);
            cpa16(bb + so, Bg + (size_t)r * Kp + c * 8);
        }
        asm volatile("cp.async.commit_group;" ::: "memory");
    };

    // prologue: 2 stages in flight
    load_tile(0, 0);
    load_tile(1, 1);

    const int lm = lane & 15, lh = lane >> 4;

    for (int kt = 0; kt < NT; kt++) {
        if (kt + 1 < NT)
            asm volatile("cp.async.wait_group 1;" ::: "memory");
        else
            asm volatile("cp.async.wait_group 0;" ::: "memory");
        __syncthreads();

        // issue next-next stage (safe: all warps done reading that slot)
        if (kt + 2 < NT) {
            int buf = (kt + 2) % NSTG;
            load_tile(kt + 2, buf);
        }

        uint32_t ab = sb + (kt % NSTG) * (2 * TILEB);
        uint32_t bb = ab + TILEB;
        uint32_t aAddr = ab + (uint32_t)((warpM + lm) * ROWB + lh * 16);
        uint32_t bAddr = bb + (uint32_t)((warpN + lm) * ROWB + lh * 16);

        #pragma unroll
        for (int ks = 0; ks < 4; ks++) {
            uint32_t afr[4][4];
            #pragma unroll
            for (int mf = 0; mf < 4; mf++)
                ldm4(aAddr + mf * 16 * ROWB + ks * 32,
                     afr[mf][0], afr[mf][1], afr[mf][2], afr[mf][3]);
            uint32_t bfr[4][2];
            #pragma unroll
            for (int nb = 0; nb < 2; nb++) {
                uint32_t r0, r1, r2, r3;
                ldm4(bAddr + nb * 16 * ROWB + ks * 32, r0, r1, r2, r3);
                bfr[nb * 2 + 0][0] = r0; bfr[nb * 2 + 0][1] = r2;
                bfr[nb * 2 + 1][0] = r1; bfr[nb * 2 + 1][1] = r3;
            }
            #pragma unroll
            for (int mf = 0; mf < 4; mf++)
                #pragma unroll
                for (int nf = 0; nf < 4; nf++)
                    mma_bf16(acc[mf][nf], afr[mf], bfr[nf][0], bfr[nf][1]);
        }
    }

    #pragma unroll
    for (int mf = 0; mf < 4; mf++) {
        int grow = brow + warpM + mf * 16 + (lane >> 2);
        #pragma unroll
        for (int nf = 0; nf < 4; nf++) {
            int gcol = bcol + warpN + nf * 8 + (lane & 3) * 2;
            float bx = bias[gcol], by = bias[gcol + 1];
            float* d = acc[mf][nf];
            float2 v0 = {d[0] + bx, d[1] + by};
            float2 v1 = {d[2] + bx, d[3] + by};
            *(float2*)&C[(size_t)grow * Ndim + gcol] = v0;
            *(float2*)&C[(size_t)(grow + 8) * Ndim + gcol] = v1;
        }
    }
}

// ============================================================
// RoPE + hi/lo split scatter (q pre-scaled by 0.125*log2 e)
// ============================================================
__global__ __launch_bounds__(256) void rope_split_kernel()
{
    int idx = blockIdx.x * blockDim.x + threadIdx.x;
    int i = idx & 31;
    int s = (idx >> 5)  & (Sn - 1);
    int h = (idx >> 15) & (Hn - 1);
    int b =  idx >> 19;

    const float* row = g_qkv + (size_t)(b * Sn + s) * N1;
    int base = h * Dn;

    float inv = expf(-(logf(10000.f) / Dn) * (2.f * i));
    float ang = (float)s * inv;
    float sn, cs;
    sincosf(ang, &sn, &cs);

    float q1 = row[0*Cn + base + i];
    float q2 = row[0*Cn + base + i + 32];
    float k1 = row[1*Cn + base + i];
    float k2 = row[1*Cn + base + i + 32];
    float v1 = row[2*Cn + base + i];
    float v2 = row[2*Cn + base + i + 32];

    const float QS = 0.18033688011112042f;  // 0.125 * log2(e)

    float qa = (q1 * cs - q2 * sn) * QS;
    float qb = (q2 * cs + q1 * sn) * QS;
    float ka = k1 * cs - k2 * sn;
    float kb = k2 * cs + k1 * sn;

    size_t o = ((size_t)(b * Hn + h) * Sn + s) * Dn;
    __nv_bfloat16 hh, ll;
    split2(qa, hh, ll); g_qh[o + i] = hh;      g_ql[o + i] = ll;
    split2(qb, hh, ll); g_qh[o + i + 32] = hh; g_ql[o + i + 32] = ll;
    split2(ka, hh, ll); g_kh[o + i] = hh;      g_kl[o + i] = ll;
    split2(kb, hh, ll); g_kh[o + i + 32] = hh; g_kl[o + i + 32] = ll;
    split2(v1, hh, ll); g_vh[o + i] = hh;      g_vl[o + i] = ll;
    split2(v2, hh, ll); g_vh[o + i + 32] = hh; g_vl[o + i + 32] = ll;
}

// ============================================================
// HMMA flash attention with 3-product hi/lo splits.
// ============================================================
#define AT_ROWB 144
#define AT_TILE (128 * AT_ROWB)
#define AT_STAGE (4 * AT_TILE)
#define AT_SMEM (2 * AT_TILE + 2 * AT_STAGE)

__global__ __launch_bounds__(256, 1) void attn_mma()
{
    extern __shared__ char smraw[];
    const uint32_t sb = smem_u32(smraw);
    const int tid = threadIdx.x, wid = tid >> 5, lane = tid & 31;
    const int bh = blockIdx.y;
    const int q0 = blockIdx.x * 128;
    const size_t bhoff = (size_t)bh * Sn * Dn;

    const uint32_t qhi_s = sb;
    const uint32_t qlo_s = sb + AT_TILE;
    const uint32_t stage0 = sb + 2 * AT_TILE;

    {
        const __nv_bfloat16* Qh = g_qh + bhoff + (size_t)q0 * Dn;
        const __nv_bfloat16* Ql = g_ql + bhoff + (size_t)q0 * Dn;
        #pragma unroll
        for (int i = 0; i < 4; i++) {
            int slot = i * 256 + tid;
            int r = slot >> 3, c = slot & 7;
            uint32_t so = (uint32_t)(r * AT_ROWB + c * 16);
            cpa16(qhi_s + so, Qh + (size_t)r * Dn + c * 8);
            cpa16(qlo_s + so, Ql + (size_t)r * Dn + c * 8);
        }
    }
    auto load_kv = [&](int t, int buf) {
        uint32_t st = stage0 + buf * AT_STAGE;
        const __nv_bfloat16* Kh = g_kh + bhoff + (size_t)t * 128 * Dn;
        const __nv_bfloat16* Kl = g_kl + bhoff + (size_t)t * 128 * Dn;
        const __nv_bfloat16* Vh = g_vh + bhoff + (size_t)t * 128 * Dn;
        const __nv_bfloat16* Vl = g_vl + bhoff + (size_t)t * 128 * Dn;
        #pragma unroll
        for (int i = 0; i < 4; i++) {
            int slot = i * 256 + tid;
            int r = slot >> 3, c = slot & 7;
            uint32_t so = (uint32_t)(r * AT_ROWB + c * 16);
            size_t go = (size_t)r * Dn + c * 8;
            cpa16(st + so, Kh + go);
            cpa16(st + AT_TILE + so, Kl + go);
            cpa16(st + 2 * AT_TILE + so, Vh + go);
            cpa16(st + 3 * AT_TILE + so, Vl + go);
        }
        asm volatile("cp.async.commit_group;" ::: "memory");
    };
    load_kv(0, 0);

    asm volatile("cp.async.wait_group 0;" ::: "memory");
    __syncthreads();

    const int lm = lane & 15, lh = lane >> 4;
    uint32_t qh[4][4], ql[4][4];
    {
        uint32_t a = (uint32_t)((wid * 16 + lm) * AT_ROWB + lh * 16);
        #pragma unroll
        for (int ks = 0; ks < 4; ks++) {
            ldm4(qhi_s + a + ks * 32, qh[ks][0], qh[ks][1], qh[ks][2], qh[ks][3]);
            ldm4(qlo_s + a + ks * 32, ql[ks][0], ql[ks][1], ql[ks][2], ql[ks][3]);
        }
    }

    float o[8][4];
    #pragma unroll
    for (int i = 0; i < 8; i++)
        #pragma unroll
        for (int e = 0; e < 4; e++) o[i][e] = 0.f;
    float m0 = -1e30f, m1 = -1e30f, ps0 = 0.f, ps1 = 0.f;

    for (int t = 0; t < 8; t++) {
        if (t > 0) {
            asm volatile("cp.async.wait_group 0;" ::: "memory");
            __syncthreads();
        }
        if (t < 7) load_kv(t + 1, (t + 1) & 1);

        uint32_t st = stage0 + (t & 1) * AT_STAGE;
        uint32_t kh_s = st, kl_s = st + AT_TILE;
        uint32_t vh_s = st + 2 * AT_TILE, vl_s = st + 3 * AT_TILE;

        float sc[16][4];
        #pragma unroll
        for (int f = 0; f < 16; f++)
            #pragma unroll
            for (int e = 0; e < 4; e++) sc[f][e] = 0.f;

        uint32_t bbase = (uint32_t)(lm * AT_ROWB + lh * 16);
        #pragma unroll
        for (int nb = 0; nb < 8; nb++) {
            uint32_t ah = kh_s + bbase + nb * 16 * AT_ROWB;
            uint32_t al = kl_s + bbase + nb * 16 * AT_ROWB;
            #pragma unroll
            for (int ks = 0; ks < 4; ks++) {
                uint32_t h0, h1, h2, h3, l0, l1, l2, l3;
                ldm4(ah + ks * 32, h0, h1, h2, h3);
                ldm4(al + ks * 32, l0, l1, l2, l3);
                mma_bf16(sc[2 * nb],     qh[ks], h0, h2);
                mma_bf16(sc[2 * nb],     ql[ks], h0, h2);
                mma_bf16(sc[2 * nb],     qh[ks], l0, l2);
                mma_bf16(sc[2 * nb + 1], qh[ks], h1, h3);
                mma_bf16(sc[2 * nb + 1], ql[ks], h1, h3);
                mma_bf16(sc[2 * nb + 1], qh[ks], l1, l3);
            }
        }

        float mx0 = -1e30f, mx1 = -1e30f;
        #pragma unroll
        for (int f = 0; f < 16; f++) {
            mx0 = fmaxf(mx0, fmaxf(sc[f][0], sc[f][1]));
            mx1 = fmaxf(mx1, fmaxf(sc[f][2], sc[f][3]));
        }
        mx0 = fmaxf(mx0, __shfl_xor_sync(0xffffffffu, mx0, 1));
        mx0 = fmaxf(mx0, __shfl_xor_sync(0xffffffffu, mx0, 2));
        mx1 = fmaxf(mx1, __shfl_xor_sync(0xffffffffu, mx1, 1));
        mx1 = fmaxf(mx1, __shfl_xor_sync(0xffffffffu, mx1, 2));

        float mn0 = fmaxf(m0, mx0), mn1 = fmaxf(m1, mx1);
        float f0 = ex2(m0 - mn0), f1 = ex2(m1 - mn1);
        m0 = mn0; m1 = mn1;
        ps0 *= f0; ps1 *= f1;
        #pragma unroll
        for (int nf = 0; nf < 8; nf++) {
            o[nf][0] *= f0; o[nf][1] *= f0;
            o[nf][2] *= f1; o[nf][3] *= f1;
        }

        uint32_t pa_hi[8][4], pa_lo[8][4];
        #pragma unroll
        for (int t2 = 0; t2 < 8; t2++) {
            #pragma unroll
            for (int half = 0; half < 2; half++) {
                int f = 2 * t2 + half;
                float p0 = ex2(sc[f][0] - m0);
                float p1 = ex2(sc[f][1] - m0);
                float p2 = ex2(sc[f][2] - m1);
                float p3 = ex2(sc[f][3] - m1);
                ps0 += p0 + p1; ps1 += p2 + p3;
                __nv_bfloat16 h0, l0, h1, l1, h2, l2, h3, l3;
                split2(p0, h0, l0); split2(p1, h1, l1);
                split2(p2, h2, l2); split2(p3, h3, l3);
                pa_hi[t2][half * 2 + 0] = packbf(h0, h1);
                pa_hi[t2][half * 2 + 1] = packbf(h2, h3);
                pa_lo[t2][half * 2 + 0] = packbf(l0, l1);
                pa_lo[t2][half * 2 + 1] = packbf(l2, l3);
            }
        }

        #pragma unroll
        for (int t2 = 0; t2 < 8; t2++) {
            uint32_t vrow = (uint32_t)((t2 * 16 + lm) * AT_ROWB + lh * 16);
            #pragma unroll
            for (int dn = 0; dn < 4; dn++) {
                uint32_t h0, h1, h2, h3, l0, l1, l2, l3;
                ldm4t(vh_s + vrow + dn * 32, h0, h1, h2, h3);
                ldm4t(vl_s + vrow + dn * 32, l0, l1, l2, l3);
                mma_bf16(o[2 * dn],     pa_hi[t2], h0, h1);
                mma_bf16(o[2 * dn],     pa_lo[t2], h0, h1);
                mma_bf16(o[2 * dn],     pa_hi[t2], l0, l1);
                mma_bf16(o[2 * dn + 1], pa_hi[t2], h2, h3);
                mma_bf16(o[2 * dn + 1], pa_lo[t2], h2, h3);
                mma_bf16(o[2 * dn + 1], pa_hi[t2], l2, l3);
            }
        }
    }

    ps0 += __shfl_xor_sync(0xffffffffu, ps0, 1);
    ps0 += __shfl_xor_sync(0xffffffffu, ps0, 2);
    ps1 += __shfl_xor_sync(0xffffffffu, ps1, 1);
    ps1 += __shfl_xor_sync(0xffffffffu, ps1, 2);
    float inv0 = 1.f / ps0, inv1 = 1.f / ps1;

    const int bidx = bh >> 4, hidx = bh & 15;
    const int grow = bidx * Sn + q0 + wid * 16 + (lane >> 2);

    #pragma unroll
    for (int nf = 0; nf < 8; nf++) {
        int col = hidx * 64 + nf * 8 + (lane & 3) * 2;
        float v0 = o[nf][0] * inv0, v1 = o[nf][1] * inv0;
        float v2 = o[nf][2] * inv1, v3 = o[nf][3] * inv1;
        __nv_bfloat16 h0, l0, h1, l1, h2, l2, h3, l3;
        split2(v0, h0, l0); split2(v1, h1, l1);
        split2(v2, h2, l2); split2(v3, h3, l3);
        uint32_t hp0 = packbf(h0, h1), lp0 = packbf(l0, l1);
        uint32_t hp1 = packbf(h2, h3), lp1 = packbf(l2, l3);
        size_t r0 = (size_t)grow * KP + col;
        size_t r1 = (size_t)(grow + 8) * KP + col;
        *(uint32_t*)&g_A3[r0]        = hp0;
        *(uint32_t*)&g_A3[r0 + 1024] = lp0;
        *(uint32_t*)&g_A3[r0 + 2048] = hp0;
        *(uint32_t*)&g_A3[r1]        = hp1;
        *(uint32_t*)&g_A3[r1 + 1024] = lp1;
        *(uint32_t*)&g_A3[r1 + 2048] = hp1;
    }
}

// ============================================================
// Launch
// ============================================================
extern "C" void kernel_launch(void* const* d_in, const int* in_sizes, int n_in,
                              void* d_out, int out_size)
{
    const float* x      = (const float*)d_in[0];
    const float* W_qkv  = (const float*)d_in[1];
    const float* b_qkv  = (const float*)d_in[2];
    const float* W_proj = (const float*)d_in[3];
    const float* b_proj = (const float*)d_in[4];
    float* out = (float*)d_out;

    cudaFuncSetAttribute(gemm_mma, cudaFuncAttributeMaxDynamicSharedMemorySize, GM_SMEM);
    cudaFuncSetAttribute(attn_mma, cudaFuncAttributeMaxDynamicSharedMemorySize, AT_SMEM);

    float* p_qkv;
    __nv_bfloat16 *p_A3, *p_B3;
    cudaGetSymbolAddress((void**)&p_qkv, g_qkv);
    cudaGetSymbolAddress((void**)&p_A3, g_A3);
    cudaGetSymbolAddress((void**)&p_B3, g_B3);

    // 1) split-convert x and W_qkv
    conv_A<<<(Mn * Cn) / 256, 256>>>(x, p_A3, Cn);
    {
        dim3 g(Cn / 32, N1 / 32);
        conv_B<<<g, 256>>>(W_qkv, p_B3, Cn, N1);
    }
    // 2) QKV GEMM (HMMA)
    {
        dim3 g(N1 / 128, Mn / 128);
        gemm_mma<<<g, 256, GM_SMEM>>>(p_A3, p_B3, b_qkv, p_qkv, N1, KP);
    }
    // 3) RoPE + hi/lo split
    rope_split_kernel<<<(Bn * Hn * Sn * 32) / 256, 256>>>();
    // 4) HMMA flash attention -> writes split A3 directly
    {
        dim3 g(Sn / 128, Bn * Hn);
        attn_mma<<<g, 256, AT_SMEM>>>();
    }
    // 5) split-convert W_proj
    {
        dim3 g(Cn / 32, Cn / 32);
        conv_B<<<g, 256>>>(W_proj, p_B3, Cn, Cn);
    }
    // 6) output projection (HMMA)
    {
        dim3 g(Cn / 128, Mn / 128);
        gemm_mma<<<g, 256, GM_SMEM>>>(p_A3, p_B3, b_proj, out, Cn, KP);
    }
}